// round 6
// baseline (speedup 1.0000x reference)
#include <cuda_runtime.h>

#define HEADS 4
#define C 32
#define F 128
#define NEG_SLOPE 0.02f
#define MAXN 50000
#define MAXE 800000

// Scratch (no allocs allowed)
__device__ int2  g_eij[MAXE];            // packed (i, j) per edge
__device__ int   g_srt[MAXE];            // source j per edge, grouped by target i
__device__ int   g_hist[MAXN];
__device__ int   g_off[MAXN + 1];
__device__ int   g_cur[MAXN];
__device__ float g_s0[MAXN * HEADS];     // dot(x[n,h,:], W[0:32])   (target term)
__device__ float g_s1[MAXN * HEADS];     // dot(x[n,h,:], W[32:64])  (source term)
__device__ int   g_is64;

// Kernel 0: detect edge_index dtype (int64 -> odd 32-bit words are all 0)
__global__ void k_detect(const unsigned int* __restrict__ w) {
    __shared__ unsigned int acc;
    if (threadIdx.x == 0) acc = 0u;
    __syncthreads();
    unsigned int local = 0u;
    for (int k = threadIdx.x; k < 8192; k += blockDim.x)
        local |= w[2 * k + 1];
    atomicOr(&acc, local);
    __syncthreads();
    if (threadIdx.x == 0) g_is64 = (acc == 0u) ? 1 : 0;
}

// Kernel 1: zero degree histogram
__global__ void k_zero(int N) {
    int t = blockIdx.x * blockDim.x + threadIdx.x;
    if (t < N) g_hist[t] = 0;
}

// Kernel 2: convert edge_index -> int2, histogram targets
__global__ void k_convert(const void* __restrict__ ei, int E) {
    int e = blockIdx.x * blockDim.x + threadIdx.x;
    if (e >= E) return;
    int i, j;
    if (g_is64) {
        const long long* p = (const long long*)ei;
        i = (int)p[e];
        j = (int)p[(size_t)E + e];
    } else {
        const int* p = (const int*)ei;
        i = p[e];
        j = p[E + e];
    }
    g_eij[e] = make_int2(i, j);
    atomicAdd(&g_hist[i], 1);
}

// Kernel 3: per-(node,head) scores s0/s1
__global__ void k_scores(const float* __restrict__ x, const float* __restrict__ W, int N) {
    int t = blockIdx.x * blockDim.x + threadIdx.x;
    if (t >= N * HEADS) return;
    int n = t >> 2;
    int h = t & 3;
    const float4* xr = (const float4*)(x + (size_t)n * F + h * C);
    const float4* w0 = (const float4*)W;
    const float4* w1 = (const float4*)(W + C);
    float s0 = 0.f, s1 = 0.f;
#pragma unroll
    for (int q = 0; q < 8; q++) {
        float4 v = xr[q];
        float4 a = w0[q];
        float4 b = w1[q];
        s0 += v.x * a.x + v.y * a.y + v.z * a.z + v.w * a.w;
        s1 += v.x * b.x + v.y * b.y + v.z * b.z + v.w * b.w;
    }
    g_s0[t] = s0;
    g_s1[t] = s1;
}

// Kernel 4: single-block exclusive scan over g_hist -> g_off, g_cur
__global__ void k_scan(int N) {
    __shared__ int sh[1024];
    int tid = threadIdx.x;
    int per = (N + 1023) / 1024;
    int base = tid * per;
    int sum = 0;
    for (int k = 0; k < per; k++)
        if (base + k < N) sum += g_hist[base + k];
    sh[tid] = sum;
    __syncthreads();
    for (int off = 1; off < 1024; off <<= 1) {
        int v = (tid >= off) ? sh[tid - off] : 0;
        __syncthreads();
        sh[tid] += v;
        __syncthreads();
    }
    int run = sh[tid] - sum;  // exclusive prefix
    for (int k = 0; k < per; k++) {
        if (base + k < N) {
            int c = g_hist[base + k];
            g_off[base + k] = run;
            g_cur[base + k] = run;
            run += c;
        }
    }
    if (tid == 1023) g_off[N] = sh[1023];
}

// Kernel 5: scatter sources into CSR order
__global__ void k_scatter(int E) {
    int e = blockIdx.x * blockDim.x + threadIdx.x;
    if (e >= E) return;
    int2 ij = g_eij[e];
    int pos = atomicAdd(&g_cur[ij.x], 1);
    g_srt[pos] = ij.y;
}

// Kernel 6: one warp per node. Pass 1: softmax denominator via warp reduce.
// Pass 2: weighted gather-accumulate in registers, single store. No atomics.
__global__ void k_agg(const float* __restrict__ x, float* __restrict__ out, int N) {
    int t = blockIdx.x * blockDim.x + threadIdx.x;
    int n = t >> 5;
    int lane = t & 31;
    if (n >= N) return;
    int start = g_off[n], end = g_off[n + 1];
    float4 s0n = *(const float4*)&g_s0[n * 4];

    // Pass 1: denom per head (lanes stride over edges, coalesced)
    float4 d = make_float4(0.f, 0.f, 0.f, 0.f);
    for (int e = start + lane; e < end; e += 32) {
        int j = g_srt[e];
        float4 sj = *(const float4*)&g_s1[j * 4];
        float a0 = s0n.x + sj.x, a1 = s0n.y + sj.y, a2 = s0n.z + sj.z, a3 = s0n.w + sj.w;
        a0 = a0 >= 0.f ? a0 : NEG_SLOPE * a0;
        a1 = a1 >= 0.f ? a1 : NEG_SLOPE * a1;
        a2 = a2 >= 0.f ? a2 : NEG_SLOPE * a2;
        a3 = a3 >= 0.f ? a3 : NEG_SLOPE * a3;
        d.x += __expf(a0);
        d.y += __expf(a1);
        d.z += __expf(a2);
        d.w += __expf(a3);
    }
#pragma unroll
    for (int o = 16; o; o >>= 1) {
        d.x += __shfl_xor_sync(0xFFFFFFFFu, d.x, o);
        d.y += __shfl_xor_sync(0xFFFFFFFFu, d.y, o);
        d.z += __shfl_xor_sync(0xFFFFFFFFu, d.z, o);
        d.w += __shfl_xor_sync(0xFFFFFFFFu, d.w, o);
    }

    // Pass 2: lane owns float4 chunk q; head h = q>>3
    int q = lane;
    int h = q >> 3;
    float s0h = (h == 0) ? s0n.x : (h == 1) ? s0n.y : (h == 2) ? s0n.z : s0n.w;
    float dh  = (h == 0) ? d.x   : (h == 1) ? d.y   : (h == 2) ? d.z   : d.w;
    float rdh = 1.0f / (dh + 1e-16f);
    float4 acc = make_float4(0.f, 0.f, 0.f, 0.f);
    for (int e = start; e < end; e++) {
        int j = g_srt[e];                 // uniform across warp -> broadcast
        float s1h = g_s1[j * 4 + h];
        float a = s0h + s1h;
        a = a >= 0.f ? a : NEG_SLOPE * a;
        float w = __expf(a) * rdh;
        float4 v = *(const float4*)(x + (size_t)j * F + q * 4);
        acc.x += v.x * w;
        acc.y += v.y * w;
        acc.z += v.z * w;
        acc.w += v.w * w;
    }
    *(float4*)(out + (size_t)n * F + q * 4) = acc;
}

extern "C" void kernel_launch(void* const* d_in, const int* in_sizes, int n_in,
                              void* d_out, int out_size) {
    const float* x = nullptr;
    const void* ei = nullptr;
    const float* W = nullptr;
    int N = 50000, E = 800000;
    for (int k = 0; k < n_in; k++) {
        int s = in_sizes[k];
        if (s == 64) {
            W = (const float*)d_in[k];
        } else if (s < 4000000) {
            ei = d_in[k];
            E = s / 2;
        } else {
            x = (const float*)d_in[k];
            N = s / F;
        }
    }
    float* out = (float*)d_out;

    const int TB = 256;
    k_detect<<<1, 256>>>((const unsigned int*)ei);
    k_zero<<<(N + TB - 1) / TB, TB>>>(N);
    k_convert<<<(E + TB - 1) / TB, TB>>>(ei, E);
    k_scores<<<(N * HEADS + TB - 1) / TB, TB>>>(x, W, N);
    k_scan<<<1, 1024>>>(N);
    k_scatter<<<(E + TB - 1) / TB, TB>>>(E);
    long long aggThreads = (long long)N * 32;
    k_agg<<<(int)((aggThreads + TB - 1) / TB), TB>>>(x, out, N);
}